// round 1
// baseline (speedup 1.0000x reference)
#include <cuda_runtime.h>
#include <math.h>

#define BB 32
#define CC 64
#define NN 16384
#define SPLITS 64   // N-splits for Gram partials; Nc = NN/SPLITS = 256

// ---------------- device scratch (no dynamic allocation allowed) ----------------
__device__ float g_coef;                          // gamma / sigma
__device__ float g_Gpart[SPLITS][BB][CC * CC];    // 32 MB partial Grams
__device__ float g_Mdup[BB][CC][2 * CC];          // M duplicated: [b][d][2c],[2c+1] = M[c][d]

// packed fp32x2 FMA (Blackwell): d = a*b + c lane-wise on two packed floats
__device__ __forceinline__ unsigned long long ffma2(unsigned long long a,
                                                    unsigned long long b,
                                                    unsigned long long c) {
    unsigned long long d;
    asm("fma.rn.f32x2 %0, %1, %2, %3;" : "=l"(d) : "l"(a), "l"(b), "l"(c));
    return d;
}

// ---------------- K1: spectral norm power iteration -> g_coef ----------------
__global__ void k_spectral(const float* __restrict__ W, const float* __restrict__ u,
                           const float* __restrict__ gamma) {
    __shared__ float sW[CC * CC];
    __shared__ float su[CC];
    __shared__ float sv[CC];
    __shared__ float red[CC];
    __shared__ float bc;
    int t = threadIdx.x;  // 64 threads
    for (int i = t; i < CC * CC; i += CC) sW[i] = W[i];
    su[t] = u[t];
    __syncthreads();

    // t_j = (W^T u)_j
    float tj = 0.f;
    #pragma unroll 8
    for (int i = 0; i < CC; i++) tj += sW[i * CC + t] * su[i];
    red[t] = tj * tj;
    __syncthreads();
    if (t == 0) { float s = 0.f; for (int i = 0; i < CC; i++) s += red[i]; bc = sqrtf(s); }
    __syncthreads();
    float nt = fmaxf(bc, 1e-12f);
    sv[t] = tj / nt;
    __syncthreads();

    // s_i = (W v)_i
    float si = 0.f;
    #pragma unroll 8
    for (int j = 0; j < CC; j++) si += sW[t * CC + j] * sv[j];
    red[t] = si * si;
    __syncthreads();
    if (t == 0) { float s = 0.f; for (int i = 0; i < CC; i++) s += red[i]; bc = sqrtf(s); }
    __syncthreads();
    float ns = fmaxf(bc, 1e-12f);
    red[t] = (si / ns) * si;   // u2_i * s_i
    __syncthreads();
    if (t == 0) {
        float sigma = 0.f;
        for (int i = 0; i < CC; i++) sigma += red[i];
        g_coef = gamma[0] / sigma;
    }
}

// ---------------- K2: Gram partials  G_b += x_b[:, n0:n0+256] x_b^T ----------------
// grid (SPLITS, BB), 256 threads. Per-thread 4x4 output tile, f32x2 over the
// column(j) dimension. Tiles staged transposed in SMEM, plus a duplicated copy
// so the f32x2 broadcast operand comes straight from LDS.128 (no MOV dups).
__global__ __launch_bounds__(256) void k_gram(const float* __restrict__ x) {
    __shared__ __align__(16) float as[32][68];     // as[kk][c]
    __shared__ __align__(16) float asd[32][136];   // asd[kk][2c],[2c+1] = a[c] dup
    int tid = threadIdx.x;
    int b = blockIdx.y, sp = blockIdx.x;
    int n0 = sp * (NN / SPLITS);
    int tx = tid & 15, ty = tid >> 4;   // 16x16 threads, 4x4 tile each
    int kk_l = tid & 31;
    int c0 = tid >> 5;

    unsigned long long acc[4][2];
    #pragma unroll
    for (int i = 0; i < 4; i++) { acc[i][0] = 0ull; acc[i][1] = 0ull; }

    const float* xb = x + (size_t)b * CC * NN;

    for (int ch = 0; ch < (NN / SPLITS) / 32; ch++) {   // 8 chunks of 32 columns
        int nb = n0 + ch * 32;
        #pragma unroll
        for (int r = 0; r < 8; r++) {
            int c = c0 + r * 8;
            float v = xb[(size_t)c * NN + nb + kk_l];
            as[kk_l][c] = v;
            *(float2*)&asd[kk_l][2 * c] = make_float2(v, v);
        }
        __syncthreads();
        #pragma unroll
        for (int kk = 0; kk < 32; kk++) {
            ulonglong2 ac2 = *(const ulonglong2*)&as[kk][4 * tx];       // 2 f32x2: cols 4tx..4tx+3
            ulonglong2 ad0 = *(const ulonglong2*)&asd[kk][8 * ty];      // dups rows 4ty, 4ty+1
            ulonglong2 ad1 = *(const ulonglong2*)&asd[kk][8 * ty + 4];  // dups rows 4ty+2, 4ty+3
            acc[0][0] = ffma2(ad0.x, ac2.x, acc[0][0]);
            acc[0][1] = ffma2(ad0.x, ac2.y, acc[0][1]);
            acc[1][0] = ffma2(ad0.y, ac2.x, acc[1][0]);
            acc[1][1] = ffma2(ad0.y, ac2.y, acc[1][1]);
            acc[2][0] = ffma2(ad1.x, ac2.x, acc[2][0]);
            acc[2][1] = ffma2(ad1.x, ac2.y, acc[2][1]);
            acc[3][0] = ffma2(ad1.y, ac2.x, acc[3][0]);
            acc[3][1] = ffma2(ad1.y, ac2.y, acc[3][1]);
        }
        __syncthreads();
    }

    float* gp = g_Gpart[sp][b];
    #pragma unroll
    for (int i = 0; i < 4; i++) {
        int row = ty * 4 + i;
        *(ulonglong2*)(gp + row * CC + 4 * tx) = make_ulonglong2(acc[i][0], acc[i][1]);
    }
}

// ---------------- K3: reduce partials, M_b = coef * G_b @ W (store duplicated, d-major) ----------------
__global__ __launch_bounds__(256) void k_reduce_m(const float* __restrict__ W) {
    __shared__ float sG[CC * CC];
    __shared__ float sW[CC * CC];
    int b = blockIdx.x, tid = threadIdx.x;
    for (int e = tid; e < CC * CC; e += 256) {
        float s = 0.f;
        #pragma unroll
        for (int sp = 0; sp < SPLITS; sp++) s += g_Gpart[sp][b][e];
        sG[e] = s;
        sW[e] = W[e];
    }
    __syncthreads();
    float coef = g_coef;
    int c = tid >> 2, dg = tid & 3;      // each thread: row c, 16 d's
    float m[16];
    #pragma unroll
    for (int k = 0; k < 16; k++) m[k] = 0.f;
    for (int e = 0; e < CC; e++) {
        float gv = sG[c * CC + e];
        #pragma unroll
        for (int k = 0; k < 16; k++) m[k] += gv * sW[e * CC + dg * 16 + k];
    }
    #pragma unroll
    for (int k = 0; k < 16; k++) {
        int d = dg * 16 + k;
        float val = coef * m[k];
        g_Mdup[b][d][2 * c]     = val;
        g_Mdup[b][d][2 * c + 1] = val;
    }
}

// ---------------- K4: out = M_b @ x_b + x_b ----------------
// grid (NN/256, BB), 256 threads, 96KB dynamic smem.
// Thread = (nq: 4 n-columns as 2 f32x2) x (cg: 16 c-rows). FFMA2-bound inner loop.
__global__ __launch_bounds__(256, 2) void k_out(const float* __restrict__ x,
                                                float* __restrict__ out) {
    extern __shared__ __align__(16) float dsm[];
    float* Ms = dsm;             // 8192 floats: Mdup[b] ([d][2c])
    float* xs = dsm + 8192;      // 16384 floats: x tile [d][256 n]
    int tid = threadIdx.x;
    int b = blockIdx.y;
    int n0 = blockIdx.x * 256;

    const float4* msrc = (const float4*)&g_Mdup[b][0][0];
    float4* mdst = (float4*)Ms;
    #pragma unroll
    for (int r = 0; r < 8; r++) mdst[tid + r * 256] = msrc[tid + r * 256];

    const float4* xsrc = (const float4*)(x + (size_t)b * CC * NN);
    float4* xdst = (float4*)xs;
    int nf0 = n0 >> 2;
    #pragma unroll
    for (int r = 0; r < 16; r++) {
        int lin = tid + r * 256;
        int d = lin >> 6;
        int nf = lin & 63;
        xdst[lin] = xsrc[(size_t)d * (NN / 4) + nf0 + nf];
    }
    __syncthreads();

    int nq = tid & 63;   // n-quad
    int cg = tid >> 6;   // 0..3 -> c rows cg*16..cg*16+15
    unsigned long long acc[16][2];
    #pragma unroll
    for (int i = 0; i < 16; i++) { acc[i][0] = 0ull; acc[i][1] = 0ull; }

    for (int d = 0; d < CC; d++) {
        ulonglong2 xv = *(const ulonglong2*)&xs[d * 256 + nq * 4];
        const float* mrow = &Ms[d * 128 + cg * 32];
        #pragma unroll
        for (int p = 0; p < 8; p++) {
            ulonglong2 md = *(const ulonglong2*)&mrow[p * 4];  // dups for c = cg*16+2p, +2p+1
            acc[2 * p][0]     = ffma2(md.x, xv.x, acc[2 * p][0]);
            acc[2 * p][1]     = ffma2(md.x, xv.y, acc[2 * p][1]);
            acc[2 * p + 1][0] = ffma2(md.y, xv.x, acc[2 * p + 1][0]);
            acc[2 * p + 1][1] = ffma2(md.y, xv.y, acc[2 * p + 1][1]);
        }
    }

    float* ob = out + (size_t)b * CC * NN;
    #pragma unroll
    for (int i = 0; i < 16; i++) {
        int c = cg * 16 + i;
        float4 xr = *(const float4*)&xs[c * 256 + nq * 4];
        unsigned long long a0 = acc[i][0], a1 = acc[i][1];
        float4 o4;
        o4.x = __uint_as_float((unsigned)(a0 & 0xffffffffu)) + xr.x;
        o4.y = __uint_as_float((unsigned)(a0 >> 32))         + xr.y;
        o4.z = __uint_as_float((unsigned)(a1 & 0xffffffffu)) + xr.z;
        o4.w = __uint_as_float((unsigned)(a1 >> 32))         + xr.w;
        *(float4*)&ob[(size_t)c * NN + n0 + nq * 4] = o4;
    }
}

// ---------------- launcher ----------------
extern "C" void kernel_launch(void* const* d_in, const int* in_sizes, int n_in,
                              void* d_out, int out_size) {
    const float *x = nullptr, *W = nullptr, *gamma = nullptr, *u = nullptr;
    for (int i = 0; i < n_in; i++) {
        int s = in_sizes[i];
        if (s == BB * CC * NN) x = (const float*)d_in[i];
        else if (s == CC * CC) W = (const float*)d_in[i];
        else if (s == 1)       gamma = (const float*)d_in[i];
        else if (s == CC)      u = (const float*)d_in[i];
    }

    cudaFuncSetAttribute(k_out, cudaFuncAttributeMaxDynamicSharedMemorySize, 98304);

    k_spectral<<<1, CC>>>(W, u, gamma);

    dim3 g2(SPLITS, BB);
    k_gram<<<g2, 256>>>(x);

    k_reduce_m<<<BB, 256>>>(W);

    dim3 g4(NN / 256, BB);
    k_out<<<g4, 256, 98304>>>(x, (float*)d_out);
}

// round 5
// speedup vs baseline: 1.2610x; 1.2610x over previous
#include <cuda_runtime.h>
#include <math.h>

#define BB 32
#define CC 64
#define NN 16384
#define NC 512                 // n-columns per Gram CTA
#define SPLITS (NN / NC)       // 32

// ---------------- device scratch (no dynamic allocation allowed) ----------------
__device__ float g_coef;                          // gamma / sigma
__device__ float g_Gpart[SPLITS][BB][CC * CC];    // 16 MB partial Grams
__device__ float g_Mdup[BB][CC][2 * CC];          // M duplicated: [b][d][2c],[2c+1] = M[c][d]

// packed fp32x2 FMA (Blackwell): d = a*b + c lane-wise on two packed floats
__device__ __forceinline__ unsigned long long ffma2(unsigned long long a,
                                                    unsigned long long b,
                                                    unsigned long long c) {
    unsigned long long d;
    asm("fma.rn.f32x2 %0, %1, %2, %3;" : "=l"(d) : "l"(a), "l"(b), "l"(c));
    return d;
}
__device__ __forceinline__ float f2_lo(unsigned long long v) {
    return __uint_as_float((unsigned)(v & 0xffffffffull));
}
__device__ __forceinline__ float f2_hi(unsigned long long v) {
    return __uint_as_float((unsigned)(v >> 32));
}

// ---------------- K1: spectral norm power iteration -> g_coef ----------------
__global__ void k_spectral(const float* __restrict__ W, const float* __restrict__ u,
                           const float* __restrict__ gamma) {
    __shared__ float sW[CC * CC];
    __shared__ float su[CC];
    __shared__ float sv[CC];
    __shared__ float red[CC];
    __shared__ float bc;
    int t = threadIdx.x;  // 64 threads
    for (int i = t; i < CC * CC; i += CC) sW[i] = W[i];
    su[t] = u[t];
    __syncthreads();

    // t_j = (W^T u)_j
    float tj = 0.f;
    #pragma unroll 8
    for (int i = 0; i < CC; i++) tj += sW[i * CC + t] * su[i];
    red[t] = tj * tj;
    __syncthreads();
    if (t == 0) { float s = 0.f; for (int i = 0; i < CC; i++) s += red[i]; bc = sqrtf(s); }
    __syncthreads();
    float nt = fmaxf(bc, 1e-12f);
    sv[t] = tj / nt;
    __syncthreads();

    // s_i = (W v)_i
    float si = 0.f;
    #pragma unroll 8
    for (int j = 0; j < CC; j++) si += sW[t * CC + j] * sv[j];
    red[t] = si * si;
    __syncthreads();
    if (t == 0) { float s = 0.f; for (int i = 0; i < CC; i++) s += red[i]; bc = sqrtf(s); }
    __syncthreads();
    float ns = fmaxf(bc, 1e-12f);
    red[t] = (si / ns) * si;   // u2_i * s_i
    __syncthreads();
    if (t == 0) {
        float sigma = 0.f;
        for (int i = 0; i < CC; i++) sigma += red[i];
        g_coef = gamma[0] / sigma;
    }
}

// ---------------- K2: Gram partials (n-parity f32x2, no transpose) ----------------
// grid (SPLITS, BB), 128 threads. Thread (tx,ty): G rows c = ty+8i (i<8),
// cols d = tx+16j (j<4). acc[i][j] is f32x2 over even/odd n; summed at the end.
// Tile sa[c][n] stride 66 floats: c-loads broadcast (1 phase), d-loads hit
// banks 2*tx (all 32 banks once) -> conflict-free. FMA-bound by construction.
__global__ __launch_bounds__(128, 4) void k_gram(const float* __restrict__ x) {
    __shared__ __align__(16) float sa[64 * 66];
    int tid = threadIdx.x;
    int b = blockIdx.y, sp = blockIdx.x;
    int n0 = sp * NC;
    int tx = tid & 15;   // d base
    int ty = tid >> 4;   // c base (0..7)

    unsigned long long acc[8][4];
    #pragma unroll
    for (int i = 0; i < 8; i++)
        #pragma unroll
        for (int j = 0; j < 4; j++) acc[i][j] = 0ull;

    const float* xb = x + (size_t)b * CC * NN;

    for (int ch = 0; ch < NC / 64; ch++) {   // 8 chunks of 64 n
        int nb = n0 + ch * 64;
        // stage [64 c][64 n] via float2 (8B): conflict-free, coalesced
        #pragma unroll
        for (int r = 0; r < 16; r++) {
            int lin = tid + r * 128;
            int c = lin >> 5;          // 32 float2 per row
            int nf2 = lin & 31;
            float2 v = *(const float2*)&xb[(size_t)c * NN + nb + 2 * nf2];
            *(float2*)&sa[c * 66 + 2 * nf2] = v;
        }
        __syncthreads();
        #pragma unroll 4
        for (int kp = 0; kp < 32; kp++) {    // 32 n-pairs
            unsigned long long cs[8], ds[4];
            #pragma unroll
            for (int i = 0; i < 8; i++)
                cs[i] = *(const unsigned long long*)&sa[(ty + 8 * i) * 66 + 2 * kp];
            #pragma unroll
            for (int j = 0; j < 4; j++)
                ds[j] = *(const unsigned long long*)&sa[(tx + 16 * j) * 66 + 2 * kp];
            #pragma unroll
            for (int i = 0; i < 8; i++)
                #pragma unroll
                for (int j = 0; j < 4; j++)
                    acc[i][j] = ffma2(cs[i], ds[j], acc[i][j]);
        }
        __syncthreads();
    }

    float* gp = g_Gpart[sp][b];
    #pragma unroll
    for (int i = 0; i < 8; i++) {
        int row = ty + 8 * i;
        #pragma unroll
        for (int j = 0; j < 4; j++) {
            int col = tx + 16 * j;
            gp[row * CC + col] = f2_lo(acc[i][j]) + f2_hi(acc[i][j]);
        }
    }
}

// ---------------- K3: reduce partials, M_b = coef * G_b @ W (store dup, d-major) ----------------
__global__ __launch_bounds__(256) void k_reduce_m(const float* __restrict__ W) {
    __shared__ float sG[CC * CC];
    __shared__ float sW[CC * CC];
    int b = blockIdx.x, tid = threadIdx.x;
    for (int e = tid; e < CC * CC; e += 256) {
        float s = 0.f;
        #pragma unroll
        for (int sp = 0; sp < SPLITS; sp++) s += g_Gpart[sp][b][e];
        sG[e] = s;
        sW[e] = W[e];
    }
    __syncthreads();
    float coef = g_coef;
    int c = tid >> 2, dg = tid & 3;      // each thread: G row c, 16 d's
    float m[16];
    #pragma unroll
    for (int k = 0; k < 16; k++) m[k] = 0.f;
    for (int e = 0; e < CC; e++) {
        float gv = sG[c * CC + e];
        #pragma unroll
        for (int k = 0; k < 16; k++) m[k] += gv * sW[e * CC + dg * 16 + k];
    }
    #pragma unroll
    for (int k = 0; k < 16; k++) {
        int d = dg * 16 + k;
        float val = coef * m[k];
        g_Mdup[b][d][2 * c]     = val;
        g_Mdup[b][d][2 * c + 1] = val;
    }
}

// ---------------- K4: out = M_b @ x_b + x_b ----------------
// grid (NN/256, BB), 256 threads, 96KB dynamic smem, 2 CTAs/SM.
// Thread tile: 8 c-rows (cg = warp id) x 8 n (4 f32x2). Per d: 2 LDS.128 (x)
// + 4 broadcast LDS.128 (M dups) feeding 32 FFMA2 -> FMA-bound.
__global__ __launch_bounds__(256, 2) void k_out(const float* __restrict__ x,
                                                float* __restrict__ out) {
    extern __shared__ __align__(16) float dsm[];
    float* Ms = dsm;             // 8192 floats: Mdup[b] ([d][2c])
    float* xs = dsm + 8192;      // 16384 floats: x tile [d][256 n]
    int tid = threadIdx.x;
    int b = blockIdx.y;
    int n0 = blockIdx.x * 256;

    const float4* msrc = (const float4*)&g_Mdup[b][0][0];
    float4* mdst = (float4*)Ms;
    #pragma unroll
    for (int r = 0; r < 8; r++) mdst[tid + r * 256] = msrc[tid + r * 256];

    const float4* xsrc = (const float4*)(x + (size_t)b * CC * NN);
    float4* xdst = (float4*)xs;
    int nf0 = n0 >> 2;
    #pragma unroll
    for (int r = 0; r < 16; r++) {
        int lin = tid + r * 256;
        int d = lin >> 6;
        int nf = lin & 63;
        xdst[lin] = xsrc[(size_t)d * (NN / 4) + nf0 + nf];
    }
    __syncthreads();

    int nq = tid & 31;   // n-octet index: n = nq*8 .. nq*8+7
    int cg = tid >> 5;   // warp id -> c rows 8cg..8cg+7 (uniform per warp)

    unsigned long long acc[8][4];
    #pragma unroll
    for (int i = 0; i < 8; i++)
        #pragma unroll
        for (int q = 0; q < 4; q++) acc[i][q] = 0ull;

    #pragma unroll 8
    for (int d = 0; d < CC; d++) {
        ulonglong2 xv0 = *(const ulonglong2*)&xs[d * 256 + nq * 8];
        ulonglong2 xv1 = *(const ulonglong2*)&xs[d * 256 + nq * 8 + 4];
        const float* mrow = &Ms[d * 128 + cg * 16];
        #pragma unroll
        for (int p = 0; p < 4; p++) {
            ulonglong2 md = *(const ulonglong2*)&mrow[p * 4];  // dups c=8cg+2p, 8cg+2p+1
            int i0 = 2 * p, i1 = 2 * p + 1;
            acc[i0][0] = ffma2(md.x, xv0.x, acc[i0][0]);
            acc[i0][1] = ffma2(md.x, xv0.y, acc[i0][1]);
            acc[i0][2] = ffma2(md.x, xv1.x, acc[i0][2]);
            acc[i0][3] = ffma2(md.x, xv1.y, acc[i0][3]);
            acc[i1][0] = ffma2(md.y, xv0.x, acc[i1][0]);
            acc[i1][1] = ffma2(md.y, xv0.y, acc[i1][1]);
            acc[i1][2] = ffma2(md.y, xv1.x, acc[i1][2]);
            acc[i1][3] = ffma2(md.y, xv1.y, acc[i1][3]);
        }
    }

    float* ob = out + (size_t)b * CC * NN;
    #pragma unroll
    for (int i = 0; i < 8; i++) {
        int c = cg * 8 + i;
        const float* xr = &xs[c * 256 + nq * 8];
        float4 r0 = *(const float4*)&xr[0];
        float4 r1 = *(const float4*)&xr[4];
        float4 o0, o1;
        o0.x = f2_lo(acc[i][0]) + r0.x;
        o0.y = f2_hi(acc[i][0]) + r0.y;
        o0.z = f2_lo(acc[i][1]) + r0.z;
        o0.w = f2_hi(acc[i][1]) + r0.w;
        o1.x = f2_lo(acc[i][2]) + r1.x;
        o1.y = f2_hi(acc[i][2]) + r1.y;
        o1.z = f2_lo(acc[i][3]) + r1.z;
        o1.w = f2_hi(acc[i][3]) + r1.w;
        float* dst = &ob[(size_t)c * NN + n0 + nq * 8];
        *(float4*)&dst[0] = o0;
        *(float4*)&dst[4] = o1;
    }
}

// ---------------- launcher ----------------
extern "C" void kernel_launch(void* const* d_in, const int* in_sizes, int n_in,
                              void* d_out, int out_size) {
    const float *x = nullptr, *W = nullptr, *gamma = nullptr, *u = nullptr;
    for (int i = 0; i < n_in; i++) {
        int s = in_sizes[i];
        if (s == BB * CC * NN) x = (const float*)d_in[i];
        else if (s == CC * CC) W = (const float*)d_in[i];
        else if (s == 1)       gamma = (const float*)d_in[i];
        else if (s == CC)      u = (const float*)d_in[i];
    }

    cudaFuncSetAttribute(k_out, cudaFuncAttributeMaxDynamicSharedMemorySize, 98304);

    k_spectral<<<1, CC>>>(W, u, gamma);

    dim3 g2(SPLITS, BB);
    k_gram<<<g2, 128>>>(x);

    k_reduce_m<<<BB, 256>>>(W);

    dim3 g4(NN / 256, BB);
    k_out<<<g4, 256, 98304>>>(x, (float*)d_out);
}